// round 4
// baseline (speedup 1.0000x reference)
#include <cuda_runtime.h>

#define NEG_PENALTY 0.03f
#define BATCH 64
#define NCLS  2048
#define LL    1024
#define NT    1024
#define FULLM 0xffffffffu

__device__ float    g_partial[BATCH];
__device__ unsigned g_ticket = 0;   // self-resetting via atomicInc wrap

__global__ __launch_bounds__(NT)
void ranking_loss_kernel(const float* __restrict__ ranks,
                         const int*   __restrict__ labels,
                         const void*  __restrict__ ids_raw,
                         float* __restrict__ out)
{
    __shared__ float s_rank[NCLS];  // staged ranks row (coalesced load)
    __shared__ int   s_lab[NCLS];   // staged labels row
    __shared__ float s_pos[LL];     // sorted pos (padded +INF)
    __shared__ float s_neg[LL];     // neg ranks
    __shared__ float s_pre[LL];     // inclusive prefix of sorted pos
    __shared__ float s_warp[32];
    __shared__ int   s_cnt[2];
    __shared__ int   s_last;

    const int b    = blockIdx.x;
    const int tid  = threadIdx.x;
    const int lane = tid & 31;
    const int wid  = tid >> 5;

    // --- dtype sniff: int64 ids have zero high words at odd 32-bit indices ---
    const int* w32 = (const int*)ids_raw;
    const bool is64 = ((w32[201] | w32[401] | w32[601] | w32[801]) == 0);
    const long long* w64 = (const long long*)ids_raw;

    // coalesced, independent loads (MLP=5): id + 2x rank + 2x label
    int id = is64 ? (int)w64[tid] : w32[tid];
    const float* rrow = ranks  + b * NCLS;
    const int*   lrow = labels + b * NCLS;
    s_rank[tid]      = rrow[tid];
    s_rank[tid + LL] = rrow[tid + LL];
    s_lab[tid]       = lrow[tid];
    s_lab[tid + LL]  = lrow[tid + LL];
    if (tid < 2) s_cnt[tid] = 0;
    __syncthreads();

    // ---- smem gather + warp-aggregated partition into pos / neg ----
    {
        float r     = s_rank[id];
        bool  ispos = (s_lab[id] == 1);
        unsigned m  = __ballot_sync(FULLM, ispos);
        int npos_w  = __popc(m);
        int rank_lt = __popc(m & ((1u << lane) - 1u));
        int basep = 0, basen = 0;
        if (lane == 0) {
            basep = atomicAdd(&s_cnt[0], npos_w);
            basen = atomicAdd(&s_cnt[1], 32 - npos_w);
        }
        basep = __shfl_sync(FULLM, basep, 0);
        basen = __shfl_sync(FULLM, basen, 0);
        if (ispos) s_pos[basep + rank_lt]          = r;
        else       s_neg[basen + (lane - rank_lt)] = r;
    }
    __syncthreads();

    const int np = s_cnt[0];
    const int nn = s_cnt[1];

    if (tid >= np) s_pos[tid] = __int_as_float(0x7f800000);  // +INF pad
    __syncthreads();

    // ================= bitonic sort, 1 element / thread =================
    float x = s_pos[tid];
    #pragma unroll
    for (int k = 2; k <= 32; k <<= 1) {
        #pragma unroll
        for (int j = k >> 1; j >= 1; j >>= 1) {
            float y = __shfl_xor_sync(FULLM, x, j);
            bool up      = ((tid & k) == 0);
            bool lowhalf = ((tid & j) == 0);
            x = (lowhalf == up) ? fminf(x, y) : fmaxf(x, y);
        }
    }
    s_pos[tid] = x;
    __syncthreads();

    #pragma unroll
    for (int k = 64; k <= LL; k <<= 1) {
        for (int j = k >> 1; j >= 32; j >>= 1) {
            if (tid < LL / 2) {
                int p  = tid;
                int i  = ((p & ~(j - 1)) << 1) | (p & (j - 1));
                int ij = i | j;
                float a = s_pos[i];
                float c = s_pos[ij];
                bool up = ((i & k) == 0);
                if ((a > c) == up) { s_pos[i] = c; s_pos[ij] = a; }
            }
            __syncthreads();
        }
        x = s_pos[tid];
        #pragma unroll
        for (int j = 16; j >= 1; j >>= 1) {
            float y = __shfl_xor_sync(FULLM, x, j);
            bool up      = ((tid & k) == 0);
            bool lowhalf = ((tid & j) == 0);
            x = (lowhalf == up) ? fminf(x, y) : fmaxf(x, y);
        }
        s_pos[tid] = x;
        __syncthreads();
    }

    // ========== inclusive prefix sum of sorted pos (shuffle scan) ==========
    float v = (tid < np) ? s_pos[tid] : 0.0f;
    #pragma unroll
    for (int d = 1; d < 32; d <<= 1) {
        float t = __shfl_up_sync(FULLM, v, d);
        if (lane >= d) v += t;
    }
    if (lane == 31) s_warp[wid] = v;
    __syncthreads();
    if (wid == 0) {
        float wv = s_warp[lane];
        #pragma unroll
        for (int d = 1; d < 32; d <<= 1) {
            float t = __shfl_up_sync(FULLM, wv, d);
            if (lane >= d) wv += t;
        }
        s_warp[lane] = wv;
    }
    __syncthreads();
    float off = (wid > 0) ? s_warp[wid - 1] : 0.0f;
    s_pre[tid] = v + off;
    __syncthreads();

    // ====== per neg: closed-form contribution k*x - prefix(k) ======
    float acc = 0.0f;
    if (tid < nn) {
        float xq = s_neg[tid] + NEG_PENALTY;
        int lo = 0, hi = np;
        while (lo < hi) {
            int mid = (lo + hi) >> 1;
            if (s_pos[mid] < xq) lo = mid + 1; else hi = mid;
        }
        if (lo > 0) acc = (float)lo * xq - s_pre[lo - 1];
    }

    // ====== block reduce via shuffles ======
    #pragma unroll
    for (int d = 16; d >= 1; d >>= 1)
        acc += __shfl_down_sync(FULLM, acc, d);
    if (lane == 0) s_warp[wid] = acc;   // ordered after scan's s_warp reads by s_pre sync
    __syncthreads();
    if (wid == 0) {
        float a2 = s_warp[lane];
        #pragma unroll
        for (int d = 16; d >= 1; d >>= 1)
            a2 += __shfl_down_sync(FULLM, a2, d);
        if (lane == 0) {
            g_partial[b] = a2;
            __threadfence();
            unsigned t = atomicInc(&g_ticket, BATCH - 1);  // wraps to 0 at 63
            s_last = (t == BATCH - 1);
        }
    }
    __syncthreads();

    // last block to finish reduces the 64 partials (fixed order, deterministic)
    if (s_last && wid == 0) {
        volatile float* gp = g_partial;   // bypass L1 for cross-SM visibility
        float v2 = gp[lane] + gp[lane + 32];
        #pragma unroll
        for (int d = 16; d >= 1; d >>= 1)
            v2 += __shfl_down_sync(FULLM, v2, d);
        if (lane == 0) out[0] = v2 * (1.0f / (float)BATCH);
    }
}

extern "C" void kernel_launch(void* const* d_in, const int* in_sizes, int n_in,
                              void* d_out, int out_size)
{
    const float* ranks  = (const float*)d_in[0];   // [B, C] f32
    const int*   labels = (const int*)d_in[1];     // [B, C] i32
    const void*  ids    = d_in[2];                 // [L] i64 or i32 (sniffed)
    float* out = (float*)d_out;                    // [1] f32

    ranking_loss_kernel<<<BATCH, NT>>>(ranks, labels, ids, out);
}

// round 6
// speedup vs baseline: 1.0238x; 1.0238x over previous
#include <cuda_runtime.h>

#define NEG_PENALTY 0.03f
#define BATCH 64
#define NCLS  2048
#define LL    1024
#define NT    512
#define GRID  (BATCH * 2)
#define FULLM 0xffffffffu

__device__ float    g_partial[GRID];
__device__ unsigned g_ticket = 0;   // self-resetting via atomicInc wrap

__global__ __launch_bounds__(NT)
void ranking_loss_kernel(const float* __restrict__ ranks,
                         const int*   __restrict__ labels,
                         const void*  __restrict__ ids_raw,
                         float* __restrict__ out)
{
    __shared__ __align__(16) float s_pos[LL + 16];  // pos ranks + 1e30 pads
    __shared__ float s_neg[LL];                     // neg ranks
    __shared__ int   s_pcnt[32];                    // pos count per 32-elem round
    __shared__ int   s_pexc[32];                    // exclusive prefix of counts
    __shared__ float s_warp[16];
    __shared__ int   s_np;
    __shared__ int   s_last;

    const int b    = blockIdx.x >> 1;   // batch
    const int half = blockIdx.x & 1;    // which half of the negs this CTA owns
    const int tid  = threadIdx.x;
    const int lane = tid & 31;
    const int wid  = tid >> 5;

    // --- dtype sniff: int64 ids have zero high words at odd 32-bit indices ---
    const int* w32 = (const int*)ids_raw;
    const bool is64 = ((w32[201] | w32[401] | w32[601] | w32[801]) == 0);
    const long long* w64 = (const long long*)ids_raw;

    // independent scattered gathers, 2 elements per thread (high MLP)
    int id0 = is64 ? (int)w64[tid]      : w32[tid];
    int id1 = is64 ? (int)w64[tid + NT] : w32[tid + NT];
    const float* rrow = ranks  + b * NCLS;
    const int*   lrow = labels + b * NCLS;
    float r0 = __ldg(&rrow[id0]);
    float r1 = __ldg(&rrow[id1]);
    int   l0 = __ldg(&lrow[id0]);
    int   l1 = __ldg(&lrow[id1]);

    // ---- deterministic index-ordered partition ----
    // Element tid belongs to round wid; element tid+512 to round wid+16.
    const bool p0 = (l0 == 1);
    const bool p1 = (l1 == 1);
    const unsigned m0 = __ballot_sync(FULLM, p0);
    const unsigned m1 = __ballot_sync(FULLM, p1);
    if (lane == 0) {
        s_pcnt[wid]      = __popc(m0);
        s_pcnt[wid + 16] = __popc(m1);
    }
    __syncthreads();

    if (wid == 0) {                       // exclusive scan of 32 round counts
        int c = s_pcnt[lane];
        int inc = c;
        #pragma unroll
        for (int d = 1; d < 32; d <<= 1) {
            int t = __shfl_up_sync(FULLM, inc, d);
            if (lane >= d) inc += t;
        }
        s_pexc[lane] = inc - c;
        if (lane == 31) s_np = inc;
    }
    __syncthreads();

    const int np = s_np;
    const int nn = LL - np;
    const unsigned ltmask = (1u << lane) - 1u;
    {   // place element 0 (round = wid)
        int rlt = __popc(m0 & ltmask);
        int bp  = s_pexc[wid];
        int bn  = wid * 32 - bp;
        if (p0) s_pos[bp + rlt] = r0;
        else    s_neg[bn + (lane - rlt)] = r0;
    }
    {   // place element 1 (round = wid + 16)
        int rlt = __popc(m1 & ltmask);
        int bp  = s_pexc[wid + 16];
        int bn  = (wid + 16) * 32 - bp;
        if (p1) s_pos[bp + rlt] = r1;
        else    s_neg[bn + (lane - rlt)] = r1;
    }
    const int np_pad = (np + 15) & ~15;        // pad to multiple of 16
    if (tid < np_pad - np) s_pos[np + tid] = 1e30f;   // relu -> 0
    __syncthreads();

    // ---- dense pair evaluation (fma-throughput bound) ----
    // jlane = neg slot within this CTA's share; ph selects pos half so the
    // inner LDS is a pure 32-lane broadcast.
    const int jlane = tid & 255;
    const int ph    = tid >> 8;                // 0 or 1
    const int np_h  = np_pad >> 1;             // multiple of 8
    const float* pbase = s_pos + ph * np_h;

    const int share = (nn + 1) >> 1;
    const int start = half * share;
    const int count = min(share, nn - start);

    float acc = 0.0f;
    for (int j = jlane; j < count; j += 256) {
        float x = s_neg[start + j] + NEG_PENALTY;
        float a0 = 0.0f, a1 = 0.0f;
        for (int i = 0; i < np_h; i += 8) {
            float4 q0 = *(const float4*)(pbase + i);
            float4 q1 = *(const float4*)(pbase + i + 4);
            a0 += fmaxf(x - q0.x, 0.0f);
            a1 += fmaxf(x - q0.y, 0.0f);
            a0 += fmaxf(x - q0.z, 0.0f);
            a1 += fmaxf(x - q0.w, 0.0f);
            a0 += fmaxf(x - q1.x, 0.0f);
            a1 += fmaxf(x - q1.y, 0.0f);
            a0 += fmaxf(x - q1.z, 0.0f);
            a1 += fmaxf(x - q1.w, 0.0f);
        }
        acc += a0 + a1;
    }

    // ---- block reduce via shuffles ----
    #pragma unroll
    for (int d = 16; d >= 1; d >>= 1)
        acc += __shfl_down_sync(FULLM, acc, d);
    if (lane == 0) s_warp[wid] = acc;
    __syncthreads();
    if (wid == 0) {
        float a2 = (lane < 16) ? s_warp[lane] : 0.0f;
        #pragma unroll
        for (int d = 8; d >= 1; d >>= 1)
            a2 += __shfl_down_sync(FULLM, a2, d);
        if (lane == 0) {
            g_partial[blockIdx.x] = a2;
            __threadfence();
            unsigned t = atomicInc(&g_ticket, GRID - 1);  // wraps to 0 at 127
            s_last = (t == GRID - 1);
        }
    }
    __syncthreads();

    // last CTA reduces the 128 partials in fixed order (deterministic)
    if (s_last && wid == 0) {
        volatile float* gp = g_partial;
        float v = gp[lane] + gp[lane + 32] + gp[lane + 64] + gp[lane + 96];
        #pragma unroll
        for (int d = 16; d >= 1; d >>= 1)
            v += __shfl_down_sync(FULLM, v, d);
        if (lane == 0) out[0] = v * (1.0f / (float)BATCH);
    }
}

extern "C" void kernel_launch(void* const* d_in, const int* in_sizes, int n_in,
                              void* d_out, int out_size)
{
    const float* ranks  = (const float*)d_in[0];   // [B, C] f32
    const int*   labels = (const int*)d_in[1];     // [B, C] i32
    const void*  ids    = d_in[2];                 // [L] i64 or i32 (sniffed)
    float* out = (float*)d_out;                    // [1] f32

    ranking_loss_kernel<<<GRID, NT>>>(ranks, labels, ids, out);
}